// round 1
// baseline (speedup 1.0000x reference)
#include <cuda_runtime.h>
#include <cuda_bf16.h>
#include <math.h>
#include <float.h>

// ---------------- problem constants ----------------
#define NS    1024          // sequence length
#define DIMM  1024          // model dim
#define NHEADS 16
#define KVH   4
#define DH    64
#define GQ    4             // HEADS / KV_HEADS
#define BS    32            // block size
#define NSEL  8
#define WB    32            // N / BS (num blocks)
#define CDIM  2048          // BS*DH
#define QKVD  1536          // (16 + 2*4)*64
#define JTOT  288           // (NSEL+1)*BS

// ---------------- scratch (static device memory; no allocations) ----------------
__device__ float g_xnorm[NS * DIMM];
__device__ float g_qkv[NS * QKVD];
__device__ float g_kpe[KVH * WB * CDIM];
__device__ float g_vpe[KVH * WB * CDIM];
__device__ float g_h1k[KVH * WB * CDIM];
__device__ float g_h1v[KVH * WB * CDIM];
__device__ float g_ckmlp[KVH * WB * DH];
__device__ float g_cvmlp[KVH * WB * DH];
__device__ float g_ck[KVH * (WB + 1) * DH];
__device__ float g_cv[KVH * (WB + 1) * DH];
__device__ float g_cout[NS * NHEADS * DH];
__device__ float g_fout[NS * NHEADS * DH];
__device__ float g_gates[NS * 2 * NHEADS];
__device__ float g_opre[NS * NHEADS * DH];
__device__ int   g_sel[KVH * NS * (NSEL + 1)];
__device__ int   g_msk[KVH * NS * (NSEL + 1)];

// ---------------- helpers ----------------
__device__ __forceinline__ float wredsum(float v) {
    #pragma unroll
    for (int o = 16; o; o >>= 1) v += __shfl_xor_sync(0xffffffffu, v, o);
    return v;
}
__device__ __forceinline__ float wredmax(float v) {
    #pragma unroll
    for (int o = 16; o; o >>= 1) v = fmaxf(v, __shfl_xor_sync(0xffffffffu, v, o));
    return v;
}

// ---------------- RMSNorm ----------------
__global__ void rmsnorm_kernel(const float* __restrict__ inp, const float* __restrict__ g) {
    int n = blockIdx.x;
    const float* row = inp + (size_t)n * DIMM;
    float s = 0.f;
    for (int i = threadIdx.x; i < DIMM; i += 256) { float v = row[i]; s += v * v; }
    __shared__ float red[8];
    s = wredsum(s);
    if ((threadIdx.x & 31) == 0) red[threadIdx.x >> 5] = s;
    __syncthreads();
    float tot = 0.f;
    #pragma unroll
    for (int i = 0; i < 8; i++) tot += red[i];
    float r = rsqrtf(tot / DIMM + 1e-6f);
    for (int i = threadIdx.x; i < DIMM; i += 256)
        g_xnorm[(size_t)n * DIMM + i] = row[i] * r * g[i];
}

// ---------------- generic fp32 GEMM: C[M,Nn] = A[M,K] @ B[K,Nn] (+bias)(+relu) ----------------
__global__ void gemm_kernel(const float* __restrict__ A, const float* __restrict__ B,
                            const float* __restrict__ bias, float* __restrict__ C,
                            int M, int K, int Nn, int relu) {
    __shared__ float As[16][65];
    __shared__ float Bs[16][65];
    int tid = threadIdx.x;
    int tx = tid & 15, ty = tid >> 4;
    int m0 = blockIdx.y * 64, n0 = blockIdx.x * 64;
    float acc[4][4] = {};
    for (int k0 = 0; k0 < K; k0 += 16) {
        #pragma unroll
        for (int e = tid; e < 1024; e += 256) {
            int m = e >> 4, kk = e & 15;
            int row = m0 + m;
            As[kk][m] = (row < M) ? A[(size_t)row * K + k0 + kk] : 0.f;
        }
        #pragma unroll
        for (int e = tid; e < 1024; e += 256) {
            int kk = e >> 6, j = e & 63;
            int col = n0 + j;
            Bs[kk][j] = (col < Nn) ? B[(size_t)(k0 + kk) * Nn + col] : 0.f;
        }
        __syncthreads();
        #pragma unroll
        for (int kk = 0; kk < 16; kk++) {
            float a[4], b[4];
            #pragma unroll
            for (int i = 0; i < 4; i++) a[i] = As[kk][ty * 4 + i];
            #pragma unroll
            for (int j = 0; j < 4; j++) b[j] = Bs[kk][tx * 4 + j];
            #pragma unroll
            for (int i = 0; i < 4; i++)
                #pragma unroll
                for (int j = 0; j < 4; j++)
                    acc[i][j] += a[i] * b[j];
        }
        __syncthreads();
    }
    #pragma unroll
    for (int i = 0; i < 4; i++) {
        int row = m0 + ty * 4 + i;
        if (row >= M) continue;
        #pragma unroll
        for (int j = 0; j < 4; j++) {
            int col = n0 + tx * 4 + j;
            if (col >= Nn) continue;
            float c = acc[i][j];
            if (bias) c += bias[col];
            if (relu) c = fmaxf(c, 0.f);
            C[(size_t)row * Nn + col] = c;
        }
    }
}

// ---------------- build compress-MLP inputs: k/v + intra-block pos emb ----------------
__global__ void build_pe_kernel(const float* __restrict__ k_pos, const float* __restrict__ v_pos) {
    int idx = blockIdx.x * blockDim.x + threadIdx.x;
    if (idx >= KVH * WB * CDIM) return;
    int h = idx / (WB * CDIM);
    int r = idx % (WB * CDIM);
    int w = r / CDIM;
    int c = r % CDIM;
    int i = c / DH, d = c % DH;
    int n = w * BS + i;
    size_t kq = (size_t)n * QKVD + NHEADS * DH + h * DH + d;
    size_t vq = (size_t)n * QKVD + (NHEADS + KVH) * DH + h * DH + d;
    int pidx = h * BS * DH + i * DH + d;
    g_kpe[idx] = g_qkv[kq] + k_pos[pidx];
    g_vpe[idx] = g_qkv[vq] + v_pos[pidx];
}

// ---------------- assemble compressed K/V: prepend mem_kv ----------------
__global__ void assemble_c_kernel(const float* __restrict__ mem_kv) {
    int idx = blockIdx.x * blockDim.x + threadIdx.x;
    if (idx >= KVH * (WB + 1) * DH) return;
    int h = idx / ((WB + 1) * DH);
    int r = idx % ((WB + 1) * DH);
    int j = r / DH, d = r % DH;
    if (j == 0) {
        g_ck[idx] = mem_kv[h * DH + d];
        g_cv[idx] = mem_kv[KVH * DH + h * DH + d];
    } else {
        g_ck[idx] = g_ckmlp[(h * WB + (j - 1)) * DH + d];
        g_cv[idx] = g_cvmlp[(h * WB + (j - 1)) * DH + d];
    }
}

// ---------------- compressed attention + importance softmax + top-k selection ----------------
// block per (kv head h, query n); warp g handles query head h*4+g (q is PRE-rotary here)
__global__ void cattn_kernel() {
    int b = blockIdx.x;
    int h = b >> 10, n = b & 1023;
    int g = threadIdx.x >> 5, lane = threadIdx.x & 31;
    __shared__ float s_sims[GQ][WB + 1];
    __shared__ float s_p[GQ][WB + 1];
    __shared__ float s_imp[WB];

    int hq = h * GQ + g;
    size_t qb = (size_t)n * QKVD + hq * DH;
    float q0 = g_qkv[qb + lane];
    float q1 = g_qkv[qb + 32 + lane];
    const float* ck = g_ck + h * (WB + 1) * DH;
    const float* cv = g_cv + h * (WB + 1) * DH;

    #pragma unroll 4
    for (int j = 0; j <= WB; j++) {
        float part = q0 * ck[j * DH + lane] + q1 * ck[j * DH + 32 + lane];
        part = wredsum(part);
        if (lane == 0) s_sims[g][j] = part * 0.125f;
    }
    __syncwarp();
    // softmax over 33 entries: lane covers j=lane; lane 0 also covers j=32
    float v0 = s_sims[g][lane];
    float v1 = (lane == 0) ? s_sims[g][32] : -FLT_MAX;
    float m = wredmax(fmaxf(v0, v1));
    float e0 = expf(v0 - m);
    float e1 = (lane == 0) ? expf(v1 - m) : 0.f;
    float ssum = wredsum(e0 + e1);
    s_p[g][lane] = e0;
    if (lane == 0) s_p[g][32] = e1;
    __syncwarp();
    float acc0 = 0.f, acc1 = 0.f;
    #pragma unroll 4
    for (int j = 0; j <= WB; j++) {
        float p = s_p[g][j];
        acc0 += p * cv[j * DH + lane];
        acc1 += p * cv[j * DH + 32 + lane];
    }
    float inv = 1.f / ssum;
    g_cout[(size_t)n * (NHEADS * DH) + hq * DH + lane] = acc0 * inv;
    g_cout[(size_t)n * (NHEADS * DH) + hq * DH + 32 + lane] = acc1 * inv;

    __syncthreads();
    // importance: mean over g of scaled sims (skip mem slot), softmax over 32 blocks
    if (threadIdx.x < 32) {
        float raw = 0.25f * (s_sims[0][lane + 1] + s_sims[1][lane + 1] +
                             s_sims[2][lane + 1] + s_sims[3][lane + 1]);
        float mm = wredmax(raw);
        float e = expf(raw - mm);
        float sm = wredsum(e);
        s_imp[lane] = e / sm;
    }
    __syncwarp();
    if (threadIdx.x == 0) {
        bool used[WB];
        #pragma unroll
        for (int w = 0; w < WB; w++) used[w] = false;
        int base = (h * NS + n) * (NSEL + 1);
        for (int s = 0; s < NSEL; s++) {
            float bv = -1.f; int bi = 0;
            for (int w = 0; w < WB; w++)
                if (!used[w] && s_imp[w] > bv) { bv = s_imp[w]; bi = w; }
            used[bi] = true;
            g_sel[base + s] = bi;
            g_msk[base + s] = (bv > 1e-10f) ? 1 : 0;
        }
        g_sel[base + NSEL] = n >> 5;   // own block, always attended
        g_msk[base + NSEL] = 1;
    }
}

// ---------------- interleaved rotary, in-place on q and k regions of qkv ----------------
__global__ void rotary_kernel() {
    int n = blockIdx.x;
    for (int t = threadIdx.x; t < (NHEADS + KVH) * 32; t += blockDim.x) {
        int hh = t >> 5, i = t & 31;
        size_t base = (size_t)n * QKVD + ((hh < NHEADS) ? hh * DH : NHEADS * DH + (hh - NHEADS) * DH);
        double invf = exp(-(double)i / 32.0 * 9.210340371976184); // ln(10000)
        double fr = (double)n * invf;
        float c = (float)cos(fr), s = (float)sin(fr);
        float x0 = g_qkv[base + 2 * i], x1 = g_qkv[base + 2 * i + 1];
        g_qkv[base + 2 * i]     = x0 * c - x1 * s;
        g_qkv[base + 2 * i + 1] = x1 * c + x0 * s;
    }
}

// ---------------- fine (block-sparse) attention ----------------
// block per (h, n); warp g per grouped query head; q/k post-rotary, v raw
__global__ void fattn_kernel() {
    int b = blockIdx.x;
    int h = b >> 10, n = b & 1023;
    __shared__ int s_blk[NSEL + 1];
    __shared__ int s_mk[NSEL + 1];
    __shared__ float s_p[GQ][JTOT];
    if (threadIdx.x < NSEL + 1) {
        int base = (h * NS + n) * (NSEL + 1);
        s_blk[threadIdx.x] = g_sel[base + threadIdx.x];
        s_mk[threadIdx.x] = g_msk[base + threadIdx.x];
    }
    __syncthreads();
    int g = threadIdx.x >> 5, lane = threadIdx.x & 31;
    int hq = h * GQ + g;
    size_t qb = (size_t)n * QKVD + hq * DH;
    float q0 = g_qkv[qb + lane];
    float q1 = g_qkv[qb + 32 + lane];

    #pragma unroll 4
    for (int j = 0; j < JTOT; j++) {
        int kn = s_blk[j >> 5] * BS + (j & 31);
        size_t kb = (size_t)kn * QKVD + NHEADS * DH + h * DH;
        float part = q0 * g_qkv[kb + lane] + q1 * g_qkv[kb + 32 + lane];
        part = wredsum(part);
        if (lane == 0) s_p[g][j] = s_mk[j >> 5] ? part * 0.125f : -FLT_MAX;
    }
    __syncwarp();
    // softmax over 288 values, lane handles j = lane + 32*t
    float m = -FLT_MAX;
    #pragma unroll
    for (int t = 0; t < 9; t++) m = fmaxf(m, s_p[g][lane + 32 * t]);
    m = wredmax(m);
    float ssum = 0.f;
    #pragma unroll
    for (int t = 0; t < 9; t++) {
        float e = expf(s_p[g][lane + 32 * t] - m);
        s_p[g][lane + 32 * t] = e;
        ssum += e;
    }
    ssum = wredsum(ssum);
    __syncwarp();
    float acc0 = 0.f, acc1 = 0.f;
    #pragma unroll 4
    for (int j = 0; j < JTOT; j++) {
        float p = s_p[g][j];
        int kn = s_blk[j >> 5] * BS + (j & 31);
        size_t vb = (size_t)kn * QKVD + (NHEADS + KVH) * DH + h * DH;
        acc0 += p * g_qkv[vb + lane];
        acc1 += p * g_qkv[vb + 32 + lane];
    }
    float inv = 1.f / ssum;
    g_fout[(size_t)n * (NHEADS * DH) + hq * DH + lane] = acc0 * inv;
    g_fout[(size_t)n * (NHEADS * DH) + hq * DH + 32 + lane] = acc1 * inv;
}

// ---------------- sigmoid gate + combine branches ----------------
__global__ void combine_kernel() {
    int idx = blockIdx.x * blockDim.x + threadIdx.x;
    if (idx >= NS * NHEADS * DH) return;
    int n = idx / (NHEADS * DH);
    int hq = (idx % (NHEADS * DH)) / DH;
    float gl0 = g_gates[n * (2 * NHEADS) + 2 * hq];
    float gl1 = g_gates[n * (2 * NHEADS) + 2 * hq + 1];
    float s0 = 1.f / (1.f + expf(-gl0));
    float s1 = 1.f / (1.f + expf(-gl1));
    g_opre[idx] = s0 * g_cout[idx] + s1 * g_fout[idx];
}

// ---------------- launch ----------------
extern "C" void kernel_launch(void* const* d_in, const int* in_sizes, int n_in,
                              void* d_out, int out_size) {
    const float* inp    = (const float*)d_in[0];
    const float* gnorm  = (const float*)d_in[1];
    const float* w_qkv  = (const float*)d_in[2];
    const float* mem_kv = (const float*)d_in[3];
    const float* k_pos  = (const float*)d_in[4];
    const float* v_pos  = (const float*)d_in[5];
    const float* k_w1   = (const float*)d_in[6];
    const float* k_b1   = (const float*)d_in[7];
    const float* k_w2   = (const float*)d_in[8];
    const float* k_b2   = (const float*)d_in[9];
    const float* v_w1   = (const float*)d_in[10];
    const float* v_b1   = (const float*)d_in[11];
    const float* v_w2   = (const float*)d_in[12];
    const float* v_b2   = (const float*)d_in[13];
    const float* gate_w = (const float*)d_in[14];
    const float* gate_b = (const float*)d_in[15];
    const float* w_out  = (const float*)d_in[16];
    float* out = (float*)d_out;

    void *p_xnorm, *p_qkv, *p_kpe, *p_vpe, *p_h1k, *p_h1v, *p_ckm, *p_cvm, *p_gates, *p_opre;
    cudaGetSymbolAddress(&p_xnorm, g_xnorm);
    cudaGetSymbolAddress(&p_qkv, g_qkv);
    cudaGetSymbolAddress(&p_kpe, g_kpe);
    cudaGetSymbolAddress(&p_vpe, g_vpe);
    cudaGetSymbolAddress(&p_h1k, g_h1k);
    cudaGetSymbolAddress(&p_h1v, g_h1v);
    cudaGetSymbolAddress(&p_ckm, g_ckmlp);
    cudaGetSymbolAddress(&p_cvm, g_cvmlp);
    cudaGetSymbolAddress(&p_gates, g_gates);
    cudaGetSymbolAddress(&p_opre, g_opre);

    // 1. RMSNorm
    rmsnorm_kernel<<<NS, 256>>>(inp, gnorm);
    // 2. qkv = xnorm @ w_qkv            [1024,1024]x[1024,1536]
    gemm_kernel<<<dim3(QKVD / 64, NS / 64), 256>>>((float*)p_xnorm, w_qkv, nullptr, (float*)p_qkv, NS, DIMM, QKVD, 0);
    // 3. gates_lin = xnorm @ gate_w + b [1024,1024]x[1024,32]
    gemm_kernel<<<dim3(1, NS / 64), 256>>>((float*)p_xnorm, gate_w, gate_b, (float*)p_gates, NS, DIMM, 2 * NHEADS, 0);
    // 4. positional-embedded block inputs
    build_pe_kernel<<<(KVH * WB * CDIM + 255) / 256, 256>>>(k_pos, v_pos);
    // 5-8. compress MLPs
    gemm_kernel<<<dim3(CDIM / 64, 2), 256>>>((float*)p_kpe, k_w1, k_b1, (float*)p_h1k, KVH * WB, CDIM, CDIM, 1);
    gemm_kernel<<<dim3(1, 2), 256>>>((float*)p_h1k, k_w2, k_b2, (float*)p_ckm, KVH * WB, CDIM, DH, 0);
    gemm_kernel<<<dim3(CDIM / 64, 2), 256>>>((float*)p_vpe, v_w1, v_b1, (float*)p_h1v, KVH * WB, CDIM, CDIM, 1);
    gemm_kernel<<<dim3(1, 2), 256>>>((float*)p_h1v, v_w2, v_b2, (float*)p_cvm, KVH * WB, CDIM, DH, 0);
    // 9. prepend mem_kv
    assemble_c_kernel<<<(KVH * (WB + 1) * DH + 255) / 256, 256>>>(mem_kv);
    // 10. compressed attention + block selection (pre-rotary q)
    cattn_kernel<<<KVH * NS, 128>>>();
    // 11. rotary on q,k (in place)
    rotary_kernel<<<NS, 256>>>();
    // 12. fine sparse attention
    fattn_kernel<<<KVH * NS, 128>>>();
    // 13. gated combine
    combine_kernel<<<(NS * NHEADS * DH + 255) / 256, 256>>>();
    // 14. final projection: out = opre @ w_out   [1024,1024]x[1024,1024]
    gemm_kernel<<<dim3(DIMM / 64, NS / 64), 256>>>((float*)p_opre, w_out, nullptr, out, NS, NHEADS * DH, DIMM, 0);
}